// round 5
// baseline (speedup 1.0000x reference)
#include <cuda_runtime.h>
#include <math.h>
#include <stdint.h>

// Problem constants
#define S_ 1024
#define H_ 768
#define L_ 50
#define SW_ 10
#define D_ 2304            // 3*H
#define KGCN (L_*H_)       // 38400
#define MAXSPAN 9216
#define MAXTOPK 1024

// mma.sync GEMM tiling
#define BM 128
#define BN 128
#define BK 16
#define SMEM_STRIDE 20     // floats per row (16 + 4 pad; conflict-free, 16B aligned)
#define SPLITK 12          // GEMM1: 38400/12 = 3200 per split

// ---------------- device scratch (zero-initialized at module load) ----------
__device__ __align__(16) float g_agg[(size_t)S_*L_*H_];      // 157 MB
__device__ __align__(16) float g_cnt[S_*L_];
__device__ __align__(16) float g_gcn[S_*H_];
__device__ __align__(16) float g_emb[S_*H_];
__device__ __align__(16) float g_pscore[S_];
__device__ __align__(16) float g_spanvec[(size_t)MAXSPAN*D_];// 85 MB (pad rows stay 0)
__device__ __align__(16) float g_mscore[MAXSPAN];
__device__ __align__(16) float g_WgT[(size_t)H_*KGCN];       // WgT[n*KGCN+k] = gcn_W[k*H+n]
__device__ __align__(16) float g_W1T[(size_t)D_*D_];         // W1T[n*D+k]    = ms_W1[k*D+n]
__device__ int   g_topk[MAXTOPK];
__device__ float g_si[MAXTOPK];
__device__ float g_sj[MAXTOPK];

// ---------------- mma.sync tf32 (sm_80+ baseline PTX, valid on sm_103) ------
__device__ __forceinline__ void mma_tf32(float* c, const uint32_t* a, const uint32_t* b) {
    asm volatile(
        "mma.sync.aligned.m16n8k8.row.col.f32.tf32.tf32.f32 "
        "{%0,%1,%2,%3}, {%4,%5,%6,%7}, {%8,%9}, {%0,%1,%2,%3};"
        : "+f"(c[0]), "+f"(c[1]), "+f"(c[2]), "+f"(c[3])
        : "r"(a[0]), "r"(a[1]), "r"(a[2]), "r"(a[3]), "r"(b[0]), "r"(b[1]));
}

// ---------------- zero / scatter / transpose --------------------------------
__global__ void zero_agg_kernel() {
    size_t idx = (size_t)blockIdx.x * blockDim.x + threadIdx.x;
    size_t stride = (size_t)gridDim.x * blockDim.x;
    float4* p = reinterpret_cast<float4*>(g_agg);
    size_t n4 = (size_t)S_ * L_ * H_ / 4;
    float4 z = make_float4(0.f, 0.f, 0.f, 0.f);
    for (size_t i = idx; i < n4; i += stride) p[i] = z;
}

__global__ void zero_small_kernel() {
    int idx = blockIdx.x * blockDim.x + threadIdx.x;
    int stride = gridDim.x * blockDim.x;
    for (int i = idx; i < S_*H_; i += stride) g_gcn[i] = 0.f;
    for (int i = idx; i < S_*L_; i += stride) g_cnt[i] = 0.f;
}

__global__ void scatter_kernel(const float* __restrict__ x,
                               const int* __restrict__ edges) {
    int e = blockIdx.x;
    int src = edges[e*3+0];
    int tgt = edges[e*3+1];
    int lbl = edges[e*3+2];
    float* dst = &g_agg[((size_t)tgt * L_ + lbl) * H_];
    const float* srow = &x[(size_t)src * H_];
    for (int h = threadIdx.x; h < H_; h += blockDim.x)
        atomicAdd(&dst[h], srow[h]);
    if (threadIdx.x == 0)
        atomicAdd(&g_cnt[tgt * L_ + lbl], 1.0f);
}

// dst(C x R) = transpose of src(R x C); R,C multiples of 32
__global__ void transpose_kernel(const float* __restrict__ src,
                                 float* __restrict__ dst, int R, int C) {
    __shared__ float t[32][33];
    int c0 = blockIdx.x * 32, r0 = blockIdx.y * 32;
    int x = threadIdx.x, y = threadIdx.y;
#pragma unroll
    for (int i = 0; i < 32; i += 8)
        t[y+i][x] = src[(size_t)(r0+y+i)*C + c0 + x];
    __syncthreads();
#pragma unroll
    for (int i = 0; i < 32; i += 8)
        dst[(size_t)(c0+y+i)*R + r0 + x] = t[x][y+i];
}

// ---------------- tf32 mma.sync GEMM -----------------------------------------
// C(m0:+128, n0:+128) = A(M x K, K-major lda) @ B^T, B(N x K, K-major lda)
// MODE 0: atomicAdd result into g_gcn (split-K partials)
// MODE 1: epilogue relu(C + b1)*W2 row-sum -> atomicAdd into g_mscore
template<int MODE>
__global__ __launch_bounds__(256)
void gemm_mma_kernel(const float* __restrict__ A, const float* __restrict__ B,
                     int lda, int ktiles,
                     const float* __restrict__ b1, const float* __restrict__ W2,
                     int nspan) {
    __shared__ float As[2][BM * SMEM_STRIDE];
    __shared__ float Bs[2][BN * SMEM_STRIDE];
    __shared__ float rowsum[BM];

    int tid = threadIdx.x;
    int wid = tid >> 5;
    int lane = tid & 31;
    int wm = wid >> 2;         // 0..1 (64 rows each)
    int wn = wid & 3;          // 0..3 (32 cols each)
    int qr = lane >> 2;        // 0..7
    int qc = lane & 3;         // 0..3

    int m0 = blockIdx.y * BM;
    int n0 = blockIdx.x * BN;
    int kbase = blockIdx.z * ktiles * BK;

    if (MODE == 1 && tid < BM) rowsum[tid] = 0.f;

    float acc[4][4][4];
#pragma unroll
    for (int i = 0; i < 4; i++)
#pragma unroll
        for (int j = 0; j < 4; j++)
#pragma unroll
            for (int r = 0; r < 4; r++) acc[i][j][r] = 0.f;

    // global load mapping: 512 float4 per tile, thread handles slots tid, tid+256
    int r0a = tid >> 2, c0a = (tid & 3) * 4;          // slot tid
    int r1a = (tid + 256) >> 2, c1a = ((tid + 256) & 3) * 4;

    const float* Abase = A + (size_t)m0 * lda + kbase;
    const float* Bbase = B + (size_t)n0 * lda + kbase;

    float4 pa0 = *(const float4*)&Abase[(size_t)r0a * lda + c0a];
    float4 pa1 = *(const float4*)&Abase[(size_t)r1a * lda + c1a];
    float4 pb0 = *(const float4*)&Bbase[(size_t)r0a * lda + c0a];
    float4 pb1 = *(const float4*)&Bbase[(size_t)r1a * lda + c1a];

    for (int kt = 0; kt < ktiles; kt++) {
        int buf = kt & 1;
        *(float4*)&As[buf][r0a * SMEM_STRIDE + c0a] = pa0;
        *(float4*)&As[buf][r1a * SMEM_STRIDE + c1a] = pa1;
        *(float4*)&Bs[buf][r0a * SMEM_STRIDE + c0a] = pb0;
        *(float4*)&Bs[buf][r1a * SMEM_STRIDE + c1a] = pb1;
        __syncthreads();

        if (kt + 1 < ktiles) {
            const float* An = Abase + (kt + 1) * BK;
            const float* Bn = Bbase + (kt + 1) * BK;
            pa0 = *(const float4*)&An[(size_t)r0a * lda + c0a];
            pa1 = *(const float4*)&An[(size_t)r1a * lda + c1a];
            pb0 = *(const float4*)&Bn[(size_t)r0a * lda + c0a];
            pb1 = *(const float4*)&Bn[(size_t)r1a * lda + c1a];
        }

        const uint32_t* Asm = (const uint32_t*)&As[buf][0];
        const uint32_t* Bsm = (const uint32_t*)&Bs[buf][0];
#pragma unroll
        for (int ks = 0; ks < 2; ks++) {
            int kb = ks * 8 + qc;
            uint32_t af[4][4];
#pragma unroll
            for (int mt = 0; mt < 4; mt++) {
                int rr = wm * 64 + mt * 16 + qr;
                af[mt][0] = Asm[rr * SMEM_STRIDE + kb];
                af[mt][1] = Asm[(rr + 8) * SMEM_STRIDE + kb];
                af[mt][2] = Asm[rr * SMEM_STRIDE + kb + 4];
                af[mt][3] = Asm[(rr + 8) * SMEM_STRIDE + kb + 4];
            }
            uint32_t bf[4][2];
#pragma unroll
            for (int nt = 0; nt < 4; nt++) {
                int cc = wn * 32 + nt * 8 + qr;
                bf[nt][0] = Bsm[cc * SMEM_STRIDE + kb];
                bf[nt][1] = Bsm[cc * SMEM_STRIDE + kb + 4];
            }
#pragma unroll
            for (int mt = 0; mt < 4; mt++)
#pragma unroll
                for (int nt = 0; nt < 4; nt++)
                    mma_tf32(acc[mt][nt], af[mt], bf[nt]);
        }
        __syncthreads();
    }

    if (MODE == 0) {
#pragma unroll
        for (int mt = 0; mt < 4; mt++) {
            int rr = m0 + wm * 64 + mt * 16 + qr;
#pragma unroll
            for (int nt = 0; nt < 4; nt++) {
                int cc = n0 + wn * 32 + nt * 8 + 2 * qc;
                atomicAdd(&g_gcn[(size_t)rr * H_ + cc],       acc[mt][nt][0]);
                atomicAdd(&g_gcn[(size_t)rr * H_ + cc + 1],   acc[mt][nt][1]);
                atomicAdd(&g_gcn[(size_t)(rr+8) * H_ + cc],   acc[mt][nt][2]);
                atomicAdd(&g_gcn[(size_t)(rr+8) * H_ + cc+1], acc[mt][nt][3]);
            }
        }
    } else {
        __syncthreads();  // rowsum zero done before loop; ensure visible
#pragma unroll
        for (int mt = 0; mt < 4; mt++) {
            float rs0 = 0.f, rs1 = 0.f;
#pragma unroll
            for (int nt = 0; nt < 4; nt++) {
                int cc = n0 + wn * 32 + nt * 8 + 2 * qc;
                float bb0 = b1[cc], bb1 = b1[cc + 1];
                float ww0 = W2[cc], ww1 = W2[cc + 1];
                rs0 += fmaxf(acc[mt][nt][0] + bb0, 0.f) * ww0;
                rs0 += fmaxf(acc[mt][nt][1] + bb1, 0.f) * ww1;
                rs1 += fmaxf(acc[mt][nt][2] + bb0, 0.f) * ww0;
                rs1 += fmaxf(acc[mt][nt][3] + bb1, 0.f) * ww1;
            }
            int rl = wm * 64 + mt * 16 + qr;
            atomicAdd(&rowsum[rl], rs0);
            atomicAdd(&rowsum[rl + 8], rs1);
        }
        __syncthreads();
        if (tid < BM) {
            int r = m0 + tid;
            if (r < nspan) atomicAdd(&g_mscore[r], rowsum[tid]);
        }
    }
}

// ---------------- GCN epilogue -----------------------------------------------
__global__ void gcn_finish_kernel(const float* __restrict__ x,
                                  const float* __restrict__ gcn_b) {
    int s = blockIdx.x;
    __shared__ float scnt[L_];
    if (threadIdx.x < L_) scnt[threadIdx.x] = g_cnt[s*L_ + threadIdx.x];
    __syncthreads();
    float deg = 0.f;
#pragma unroll
    for (int l = 0; l < L_; l++) deg += scnt[l];
    deg = fmaxf(deg, 1.0f);
    float inv = 1.0f / deg;
    for (int c = threadIdx.x; c < H_; c += blockDim.x) {
        float bias = 0.f;
#pragma unroll 10
        for (int l = 0; l < L_; l++) bias += scnt[l] * gcn_b[l*H_ + c];
        float v = (g_gcn[s*H_ + c] + bias) * inv;
        v = v > 0.f ? v : 0.f;
        g_emb[s*H_ + c] = x[s*H_ + c] + v;
    }
}

__global__ void row_score_kernel(const float* __restrict__ attn_w,
                                 const float* __restrict__ attn_b) {
    int warp = threadIdx.x >> 5;
    int lane = threadIdx.x & 31;
    int s = blockIdx.x * 8 + warp;
    if (s >= S_) return;
    float p = 0.f;
    for (int h = lane; h < H_; h += 32)
        p += g_emb[s*H_ + h] * attn_w[h];
#pragma unroll
    for (int o = 16; o > 0; o >>= 1)
        p += __shfl_xor_sync(0xffffffffu, p, o);
    if (lane == 0) g_pscore[s] = p + attn_b[0];
}

__global__ void span_kernel(const int* __restrict__ starts,
                            const int* __restrict__ ends, int nspan) {
    int gwarp = (blockIdx.x * blockDim.x + threadIdx.x) >> 5;
    int lane = threadIdx.x & 31;
    if (gwarp >= nspan) return;
    int st = starts[gwarp];
    int en = ends[gwarp];

    float sc[SW_];
    int   pc[SW_];
    float m = -3.4e38f;
#pragma unroll
    for (int w = 0; w < SW_; w++) {
        int pos = st + w;
        pc[w] = pos < (S_-1) ? pos : (S_-1);
        float sv = g_pscore[pc[w]];
        if (pos > en) sv = -1e9f;
        sc[w] = sv;
        m = fmaxf(m, sv);
    }
    float denom = 0.f;
#pragma unroll
    for (int w = 0; w < SW_; w++) { sc[w] = expf(sc[w] - m); denom += sc[w]; }
    float inv = 1.0f / denom;

    float* out = &g_spanvec[(size_t)gwarp * D_];
    for (int h = lane; h < H_; h += 32) {
        float o = 0.f;
#pragma unroll
        for (int w = 0; w < SW_; w++)
            o += sc[w] * g_emb[pc[w]*H_ + h];
        out[h]        = g_emb[st*H_ + h];
        out[H_ + h]   = g_emb[en*H_ + h];
        out[2*H_ + h] = o * inv;
    }
}

__global__ void init_mscore_kernel(const float* __restrict__ ms_b2, int nspan) {
    int i = blockIdx.x * blockDim.x + threadIdx.x;
    if (i < nspan) g_mscore[i] = ms_b2[0];
}

// ---------------- exact top-k by ranking -------------------------------------
__global__ void topk_kernel(int nspan, int ktop) {
    __shared__ float sc[MAXSPAN];
    for (int i = threadIdx.x; i < MAXSPAN; i += blockDim.x)
        sc[i] = (i < nspan) ? g_mscore[i] : -3.4e38f;
    __syncthreads();
    int i = blockIdx.x * blockDim.x + threadIdx.x;
    if (i >= nspan) return;
    float si = sc[i];
    int r = 0;
    for (int j = 0; j < nspan; j++) {
        float sj = sc[j];
        r += (sj > si) || (sj == si && j < i);
    }
    if (r < ktop) g_topk[r] = i;
}

__global__ void ant_proj_kernel(const float* __restrict__ antW, int ktop) {
    int b = blockIdx.x;
    int idx = g_topk[b];
    const float* row = &g_spanvec[(size_t)idx * D_];
    float si = 0.f, sj = 0.f;
    for (int c = threadIdx.x; c < D_; c += blockDim.x) {
        float v = row[c];
        si += v * antW[c];
        sj += v * antW[D_ + c];
    }
    __shared__ float r1[256], r2[256];
    r1[threadIdx.x] = si; r2[threadIdx.x] = sj;
    __syncthreads();
    for (int o = 128; o > 0; o >>= 1) {
        if (threadIdx.x < o) {
            r1[threadIdx.x] += r1[threadIdx.x + o];
            r2[threadIdx.x] += r2[threadIdx.x + o];
        }
        __syncthreads();
    }
    if (threadIdx.x == 0) { g_si[b] = r1[0]; g_sj[b] = r2[0]; }
}

__global__ void final_kernel(float* __restrict__ out,
                             const float* __restrict__ ant_b, int ktop) {
    int id = blockIdx.x * blockDim.x + threadIdx.x;
    int total = ktop * (ktop + 1);
    if (id >= total) return;
    int i = id / (ktop + 1);
    int c = id % (ktop + 1);
    float v;
    if (c == 0) {
        v = 0.f;
    } else {
        int j = c - 1;
        v = (j >= i) ? -10000.0f : (g_si[i] + g_sj[j] + ant_b[0]);
    }
    out[id] = v;
}

// ---------------- host launch -------------------------------------------------
extern "C" void kernel_launch(void* const* d_in, const int* in_sizes, int n_in,
                              void* d_out, int out_size) {
    const float* hidden = (const float*)d_in[0];
    const int*   edges  = (const int*)d_in[1];
    const float* gcnW   = (const float*)d_in[2];
    const float* gcnb   = (const float*)d_in[3];
    const float* attnw  = (const float*)d_in[4];
    const float* attnb  = (const float*)d_in[5];
    const float* msW1   = (const float*)d_in[6];
    const float* msb1   = (const float*)d_in[7];
    const float* msW2   = (const float*)d_in[8];
    const float* msb2   = (const float*)d_in[9];
    const float* antW   = (const float*)d_in[10];
    const float* antb   = (const float*)d_in[11];
    const int*   sstart = (const int*)d_in[12];
    const int*   send   = (const int*)d_in[13];

    int E = in_sizes[1] / 3;
    int nspan = in_sizes[12];
    int ktop = (int)((sqrt(4.0 * (double)out_size + 1.0) - 1.0) / 2.0 + 0.5);
    float* out = (float*)d_out;

    zero_agg_kernel<<<2048, 256>>>();
    zero_small_kernel<<<512, 256>>>();
    scatter_kernel<<<E, 256>>>(hidden, edges);

    // weight transposes to K-major (B[n,k] = W[k,n])
    {
        dim3 blk(32, 8);
        transpose_kernel<<<dim3(H_/32, KGCN/32), blk>>>(gcnW, g_WgT, KGCN, H_);
        transpose_kernel<<<dim3(D_/32, D_/32), blk>>>(msW1, g_W1T, D_, D_);
    }

    // GEMM1: g_gcn(1024x768) += agg(1024x38400) @ gcn_W  [tf32 mma.sync, split-K 12]
    gemm_mma_kernel<0><<<dim3(H_/BN, S_/BM, SPLITK), 256>>>(
        g_agg, g_WgT, KGCN, (KGCN/BK)/SPLITK, nullptr, nullptr, 0);

    gcn_finish_kernel<<<S_, 256>>>(hidden, gcnb);
    row_score_kernel<<<S_/8, 256>>>(attnw, attnb);
    span_kernel<<<(nspan*32 + 255)/256, 256>>>(sstart, send, nspan);
    init_mscore_kernel<<<(nspan + 255)/256, 256>>>(msb2, nspan);

    // GEMM2: mention MLP fused (9216 x 2304 x 2304) [tf32 mma.sync]
    gemm_mma_kernel<1><<<dim3(D_/BN, MAXSPAN/BM, 1), 256>>>(
        g_spanvec, g_W1T, D_, D_/BK, msb1, msW2, nspan);

    topk_kernel<<<(nspan + 255)/256, 256>>>(nspan, ktop);
    ant_proj_kernel<<<ktop, 256>>>(antW, ktop);
    final_kernel<<<(ktop*(ktop+1) + 255)/256, 256>>>(out, antb, ktop);
}

// round 6
// speedup vs baseline: 13.9644x; 13.9644x over previous
#include <cuda_runtime.h>
#include <math.h>
#include <stdint.h>

// Problem constants
#define S_ 1024
#define H_ 768
#define L_ 50
#define SW_ 10
#define D_ 2304            // 3*H
#define P_N 6912           // 3*D columns of P = emb @ [W1a|W1b|W1c]
#define MAXSPAN 9216
#define MAXTOPK 1024

// SIMT fp32 GEMM tiling (proven round-2 structure)
#define BM 128
#define BN 128
#define BK 8

// ---------------- device scratch (zero-init at load; we re-zero what we reuse)
__device__ __align__(16) float g_z[(size_t)L_*S_*H_];     // 157 MB: z[l][s][d]
__device__ __align__(16) float g_P[(size_t)S_*P_N];       // 28 MB: P[s][n]
__device__ __align__(16) float g_cnt[S_*L_];
__device__ int   g_tcnt[S_];
__device__ int   g_toff[S_];
__device__ int   g_tcur[S_];
__device__ int   g_eidx[65536*2];                          // headroom for E
__device__ __align__(16) float g_emb[S_*H_];
__device__ __align__(16) float g_pscore[S_];
__device__ __align__(16) float g_aw[MAXSPAN*SW_];
__device__ __align__(16) float g_mscore[MAXSPAN];
__device__ __align__(16) float g_eabc[S_*6];
__device__ int   g_topk[MAXTOPK];
__device__ float g_si[MAXTOPK];
__device__ float g_sj[MAXTOPK];

// ---------------- zero -------------------------------------------------------
__global__ void zero_kernel() {
    int idx = blockIdx.x * blockDim.x + threadIdx.x;
    int stride = gridDim.x * blockDim.x;
    for (int i = idx; i < S_*L_; i += stride) g_cnt[i] = 0.f;
    for (int i = idx; i < S_; i += stride) { g_tcnt[i] = 0; }
}

// ---------------- edge histogram --------------------------------------------
__global__ void edge_hist_kernel(const int* __restrict__ edges, int E) {
    int e = blockIdx.x * blockDim.x + threadIdx.x;
    if (e >= E) return;
    int tgt = edges[e*3+1];
    int lbl = edges[e*3+2];
    atomicAdd(&g_cnt[tgt*L_ + lbl], 1.0f);
    atomicAdd(&g_tcnt[tgt], 1);
}

// 1 block, 1024 threads: exclusive scan of g_tcnt -> g_toff, g_tcur
__global__ void scan_kernel() {
    __shared__ int tmp[S_];
    int t = threadIdx.x;
    int v = g_tcnt[t];
    tmp[t] = v;
    __syncthreads();
    for (int o = 1; o < S_; o <<= 1) {
        int u = (t >= o) ? tmp[t-o] : 0;
        __syncthreads();
        tmp[t] += u;
        __syncthreads();
    }
    g_toff[t] = tmp[t] - v;
    g_tcur[t] = tmp[t] - v;
}

__global__ void edge_scatter_kernel(const int* __restrict__ edges, int E) {
    int e = blockIdx.x * blockDim.x + threadIdx.x;
    if (e >= E) return;
    int tgt = edges[e*3+1];
    int p = atomicAdd(&g_tcur[tgt], 1);
    g_eidx[p] = e;
}

// ---------------- SIMT fp32 GEMM: C = A(M x K, lda) @ B(K x N, ldb) ----------
// batched via blockIdx.z with element strides; direct store.
__global__ __launch_bounds__(256)
void gemm_nn_kernel(const float* __restrict__ A0, int lda,
                    const float* __restrict__ B0, int ldb,
                    float* __restrict__ C0, int ldc, int K,
                    size_t strideA, size_t strideB, size_t strideC) {
    __shared__ float As[BK][BM];
    __shared__ float Bs[BK][BN];
    int tid = threadIdx.x;
    int bx = blockIdx.x, by = blockIdx.y, bz = blockIdx.z;
    const float* A = A0 + (size_t)bz * strideA;
    const float* B = B0 + (size_t)bz * strideB;
    float* C = C0 + (size_t)bz * strideC;

    int arow = tid >> 1,  acol = (tid & 1) * 4;
    int brow = tid >> 5,  bcol = (tid & 31) * 4;
    int ty = tid >> 4,    tx = tid & 15;

    float acc[8][8];
#pragma unroll
    for (int i = 0; i < 8; i++)
#pragma unroll
        for (int j = 0; j < 8; j++) acc[i][j] = 0.f;

    const float* Aptr = &A[(size_t)(by*BM + arow) * lda];
    float4 pa = *(const float4*)&Aptr[acol];
    float4 pb = *(const float4*)&B[(size_t)brow * ldb + bx*BN + bcol];

    int iters = K / BK;
    for (int kt = 0; kt < iters; kt++) {
        As[acol+0][arow] = pa.x;
        As[acol+1][arow] = pa.y;
        As[acol+2][arow] = pa.z;
        As[acol+3][arow] = pa.w;
        *(float4*)&Bs[brow][bcol] = pb;
        __syncthreads();
        if (kt + 1 < iters) {
            int k0 = (kt+1)*BK;
            pa = *(const float4*)&Aptr[k0 + acol];
            pb = *(const float4*)&B[(size_t)(k0 + brow) * ldb + bx*BN + bcol];
        }
#pragma unroll
        for (int kk = 0; kk < BK; kk++) {
            float4 a0 = *(float4*)&As[kk][ty*4];
            float4 a1 = *(float4*)&As[kk][ty*4+64];
            float4 b0 = *(float4*)&Bs[kk][tx*4];
            float4 b1 = *(float4*)&Bs[kk][tx*4+64];
            float a[8] = {a0.x,a0.y,a0.z,a0.w,a1.x,a1.y,a1.z,a1.w};
            float b[8] = {b0.x,b0.y,b0.z,b0.w,b1.x,b1.y,b1.z,b1.w};
#pragma unroll
            for (int i = 0; i < 8; i++)
#pragma unroll
                for (int j = 0; j < 8; j++)
                    acc[i][j] += a[i]*b[j];
        }
        __syncthreads();
    }

#pragma unroll
    for (int i = 0; i < 8; i++) {
        int r = by*BM + ((i < 4) ? (ty*4 + i) : (64 + ty*4 + i - 4));
#pragma unroll
        for (int j = 0; j < 8; j++) {
            int c = bx*BN + ((j < 4) ? (tx*4 + j) : (64 + tx*4 + j - 4));
            C[(size_t)r * ldc + c] = acc[i][j];
        }
    }
}

// ------- gather + GCN epilogue: emb = x + relu((Σ z[lbl][src] + cnt@b)/deg) --
__global__ __launch_bounds__(256)
void gather_finish_kernel(const float* __restrict__ x,
                          const int* __restrict__ edges,
                          const float* __restrict__ gcn_b) {
    int s = blockIdx.x;
    int tid = threadIdx.x;
    __shared__ float scnt[L_];
    __shared__ int sedge[512];     // (src,lbl) pairs per chunk of 256 edges
    if (tid < L_) scnt[tid] = g_cnt[s*L_ + tid];
    __syncthreads();
    float deg = 0.f;
#pragma unroll
    for (int l = 0; l < L_; l++) deg += scnt[l];
    deg = fmaxf(deg, 1.0f);
    float inv = 1.0f / deg;

    float acc0 = 0.f, acc1 = 0.f, acc2 = 0.f;
    // bias term: cnt @ gcn_b
    for (int l = 0; l < L_; l++) {
        float cv = scnt[l];
        if (cv != 0.f) {
            acc0 += cv * gcn_b[l*H_ + tid];
            acc1 += cv * gcn_b[l*H_ + tid + 256];
            acc2 += cv * gcn_b[l*H_ + tid + 512];
        }
    }
    int lo = g_toff[s];
    int cntE = g_tcnt[s];
    for (int base = 0; base < cntE; base += 256) {
        int m = min(256, cntE - base);
        if (tid < m) {
            int eid = g_eidx[lo + base + tid];
            sedge[tid*2]   = edges[eid*3];
            sedge[tid*2+1] = edges[eid*3+2];
        }
        __syncthreads();
        for (int j = 0; j < m; j++) {
            const float* zr = &g_z[((size_t)sedge[j*2+1] * S_ + sedge[j*2]) * H_];
            acc0 += zr[tid];
            acc1 += zr[tid + 256];
            acc2 += zr[tid + 512];
        }
        __syncthreads();
    }
    g_emb[s*H_ + tid]       = x[s*H_ + tid]       + fmaxf(acc0 * inv, 0.f);
    g_emb[s*H_ + tid + 256] = x[s*H_ + tid + 256] + fmaxf(acc1 * inv, 0.f);
    g_emb[s*H_ + tid + 512] = x[s*H_ + tid + 512] + fmaxf(acc2 * inv, 0.f);
}

// ---------------- per-position attention score ------------------------------
__global__ void row_score_kernel(const float* __restrict__ attn_w,
                                 const float* __restrict__ attn_b) {
    int warp = threadIdx.x >> 5;
    int lane = threadIdx.x & 31;
    int s = blockIdx.x * 8 + warp;
    if (s >= S_) return;
    float p = 0.f;
    for (int h = lane; h < H_; h += 32)
        p += g_emb[s*H_ + h] * attn_w[h];
#pragma unroll
    for (int o = 16; o > 0; o >>= 1)
        p += __shfl_xor_sync(0xffffffffu, p, o);
    if (lane == 0) g_pscore[s] = p + attn_b[0];
}

// ---------------- softmax attention weights per span ------------------------
__global__ void aw_kernel(const int* __restrict__ starts,
                          const int* __restrict__ ends, int nspan) {
    int n = blockIdx.x * blockDim.x + threadIdx.x;
    if (n >= nspan) return;
    int st = starts[n], en = ends[n];
    float sc[SW_];
    float m = -3.4e38f;
#pragma unroll
    for (int w = 0; w < SW_; w++) {
        int pos = st + w;
        int pc = pos < (S_-1) ? pos : (S_-1);
        float sv = g_pscore[pc];
        if (pos > en) sv = -1e9f;
        sc[w] = sv;
        m = fmaxf(m, sv);
    }
    float denom = 0.f;
#pragma unroll
    for (int w = 0; w < SW_; w++) { sc[w] = expf(sc[w] - m); denom += sc[w]; }
    float inv = 1.0f / denom;
#pragma unroll
    for (int w = 0; w < SW_; w++) g_aw[n*SW_ + w] = sc[w] * inv;
}

// ------- mention scores: block per start position, spans share P rows -------
__global__ __launch_bounds__(256)
void mention_kernel(const int* __restrict__ starts, const int* __restrict__ ends,
                    const float* __restrict__ b1, const float* __restrict__ W2,
                    const float* __restrict__ b2p, int nspan) {
    int s = blockIdx.x;
    // binary search for span range [lo, hi) with start == s (starts sorted)
    int lo, hi;
    { int a = 0, b = nspan;
      while (a < b) { int m = (a+b) >> 1; if (starts[m] < s) a = m+1; else b = m; }
      lo = a; }
    { int a = lo, b = nspan;
      while (a < b) { int m = (a+b) >> 1; if (starts[m] < s+1) a = m+1; else b = m; }
      hi = a; }
    int cntS = hi - lo;
    if (cntS == 0) return;

    __shared__ float saw[SW_-1][SW_];    // up to 9 spans x 10 weights
    __shared__ int   sen[SW_-1];
    __shared__ float red[SW_-1];
    int tid = threadIdx.x;
    if (tid < cntS*SW_) saw[tid/SW_][tid%SW_] = g_aw[(lo + tid/SW_)*SW_ + tid%SW_];
    if (tid < cntS) { sen[tid] = ends[lo + tid]; red[tid] = 0.f; }
    __syncthreads();

    float partial[SW_-1];
#pragma unroll
    for (int j = 0; j < SW_-1; j++) partial[j] = 0.f;

    for (int c = tid; c < D_; c += 256) {
        float p1 = g_P[(size_t)s * P_N + c];
        float p3[SW_];
#pragma unroll
        for (int w = 0; w < SW_; w++) {
            int pc = (s + w) < (S_-1) ? (s + w) : (S_-1);
            p3[w] = g_P[(size_t)pc * P_N + 2*D_ + c];
        }
        float b1c = b1[c], w2c = W2[c];
        for (int j = 0; j < cntS; j++) {
            float v = p1 + g_P[(size_t)sen[j] * P_N + D_ + c];
#pragma unroll
            for (int w = 0; w < SW_; w++) v += saw[j][w] * p3[w];
            partial[j] += fmaxf(v + b1c, 0.f) * w2c;
        }
    }
    for (int j = 0; j < cntS; j++) atomicAdd(&red[j], partial[j]);
    __syncthreads();
    if (tid < cntS) g_mscore[lo + tid] = red[tid] + b2p[0];
}

// ---------------- exact top-k by ranking ------------------------------------
__global__ void topk_kernel(int nspan, int ktop) {
    __shared__ float sc[MAXSPAN];
    for (int i = threadIdx.x; i < MAXSPAN; i += blockDim.x)
        sc[i] = (i < nspan) ? g_mscore[i] : -3.4e38f;
    __syncthreads();
    int i = blockIdx.x * blockDim.x + threadIdx.x;
    if (i >= nspan) return;
    float si = sc[i];
    int r = 0;
    for (int j = 0; j < nspan; j++) {
        float sj = sc[j];
        r += (sj > si) || (sj == si && j < i);
    }
    if (r < ktop) g_topk[r] = i;
}

// ----- per-position antecedent dots: 6 projections of emb rows --------------
__global__ void eabc_kernel(const float* __restrict__ antW) {
    int s = blockIdx.x;                 // 1024 blocks, 192 threads (6 warps)
    int w = threadIdx.x >> 5;           // 0..5
    int lane = threadIdx.x & 31;
    const float* a = antW + w * H_;     // covers antW[0 : 4608)
    float p = 0.f;
    for (int h = lane; h < H_; h += 32)
        p += g_emb[s*H_ + h] * a[h];
#pragma unroll
    for (int o = 16; o > 0; o >>= 1)
        p += __shfl_xor_sync(0xffffffffu, p, o);
    if (lane == 0) g_eabc[s*6 + w] = p;
}

__global__ void sisj_kernel(const int* __restrict__ starts,
                            const int* __restrict__ ends, int ktop) {
    int b = blockIdx.x * blockDim.x + threadIdx.x;
    if (b >= ktop) return;
    int n = g_topk[b];
    int st = starts[n], en = ends[n];
    float ci = 0.f, cj = 0.f;
#pragma unroll
    for (int w = 0; w < SW_; w++) {
        int pc = (st + w) < (S_-1) ? (st + w) : (S_-1);
        float a = g_aw[n*SW_ + w];
        ci += a * g_eabc[pc*6 + 2];
        cj += a * g_eabc[pc*6 + 5];
    }
    g_si[b] = g_eabc[st*6 + 0] + g_eabc[en*6 + 1] + ci;
    g_sj[b] = g_eabc[st*6 + 3] + g_eabc[en*6 + 4] + cj;
}

__global__ void final_kernel(float* __restrict__ out,
                             const float* __restrict__ ant_b, int ktop) {
    int id = blockIdx.x * blockDim.x + threadIdx.x;
    int total = ktop * (ktop + 1);
    if (id >= total) return;
    int i = id / (ktop + 1);
    int c = id % (ktop + 1);
    float v;
    if (c == 0) {
        v = 0.f;
    } else {
        int j = c - 1;
        v = (j >= i) ? -10000.0f : (g_si[i] + g_sj[j] + ant_b[0]);
    }
    out[id] = v;
}

// ---------------- host launch -------------------------------------------------
extern "C" void kernel_launch(void* const* d_in, const int* in_sizes, int n_in,
                              void* d_out, int out_size) {
    const float* hidden = (const float*)d_in[0];
    const int*   edges  = (const int*)d_in[1];
    const float* gcnW   = (const float*)d_in[2];
    const float* gcnb   = (const float*)d_in[3];
    const float* attnw  = (const float*)d_in[4];
    const float* attnb  = (const float*)d_in[5];
    const float* msW1   = (const float*)d_in[6];
    const float* msb1   = (const float*)d_in[7];
    const float* msW2   = (const float*)d_in[8];
    const float* msb2   = (const float*)d_in[9];
    const float* antW   = (const float*)d_in[10];
    const float* antb   = (const float*)d_in[11];
    const int*   sstart = (const int*)d_in[12];
    const int*   send   = (const int*)d_in[13];

    int E = in_sizes[1] / 3;
    int nspan = in_sizes[12];
    int ktop = (int)((sqrt(4.0 * (double)out_size + 1.0) - 1.0) / 2.0 + 0.5);
    float* out = (float*)d_out;

    // device symbol addresses for GEMM args
    float* zptr;  cudaGetSymbolAddress((void**)&zptr, g_z);
    float* Pptr;  cudaGetSymbolAddress((void**)&Pptr, g_P);
    float* embp;  cudaGetSymbolAddress((void**)&embp, g_emb);

    zero_kernel<<<64, 256>>>();
    edge_hist_kernel<<<(E + 255)/256, 256>>>(edges, E);
    scan_kernel<<<1, S_>>>();
    edge_scatter_kernel<<<(E + 255)/256, 256>>>(edges, E);

    // z[l] = x @ W_l  (batched 50 x (1024x768x768), 60.4 GF)
    gemm_nn_kernel<<<dim3(H_/BN, S_/BM, L_), 256>>>(
        hidden, H_, gcnW, H_, zptr, H_, H_,
        0, (size_t)H_*H_, (size_t)S_*H_);

    gather_finish_kernel<<<S_, 256>>>(hidden, edges, gcnb);
    row_score_kernel<<<S_/8, 256>>>(attnw, attnb);
    aw_kernel<<<(nspan + 255)/256, 256>>>(sstart, send, nspan);

    // P parts: P[:, part*D : part*D+D] = emb @ ms_W1[part*768:(part+1)*768, :]
    for (int part = 0; part < 3; part++) {
        gemm_nn_kernel<<<dim3(D_/BN, S_/BM, 1), 256>>>(
            embp, H_, msW1 + (size_t)part*H_*D_, D_,
            Pptr + (size_t)part*D_, P_N, H_, 0, 0, 0);
    }

    mention_kernel<<<S_, 256>>>(sstart, send, msb1, msW2, msb2, nspan);
    topk_kernel<<<(nspan + 255)/256, 256>>>(nspan, ktop);
    eabc_kernel<<<S_, 192>>>(antW);
    sisj_kernel<<<(ktop + 255)/256, 256>>>(sstart, send, ktop);
    final_kernel<<<(ktop*(ktop+1) + 255)/256, 256>>>(out, antb, ktop);
}

// round 7
// speedup vs baseline: 14.1845x; 1.0158x over previous
#include <cuda_runtime.h>
#include <math.h>
#include <stdint.h>

// Problem constants
#define S_ 1024
#define H_ 768
#define L_ 50
#define SW_ 10
#define D_ 2304            // 3*H
#define P_N 6912           // 3*D columns of P = emb @ [W1a|W1b|W1c]
#define MAXSPAN 9216
#define MAXTOPK 1024

// SIMT fp32 GEMM tiling
#define BM 128
#define BN 128
#define BK 8

// ---------------- device scratch ---------------------------------------------
__device__ __align__(16) float g_z[(size_t)L_*S_*H_];     // 157 MB: z[l][s][d]
__device__ __align__(16) float g_P[(size_t)S_*P_N];       // 28 MB: P[s][n]
__device__ __align__(16) float g_cnt[S_*L_];
__device__ int   g_tcnt[S_];
__device__ int   g_toff[S_];
__device__ int   g_tcur[S_];
__device__ int   g_eidx[65536*2];
__device__ __align__(16) float g_emb[S_*H_];
__device__ __align__(16) float g_pscore[S_];
__device__ __align__(16) float g_aw[MAXSPAN*SW_];
__device__ __align__(16) float g_mscore[MAXSPAN];
__device__ __align__(16) float g_eabc[S_*6];
__device__ int   g_topk[MAXTOPK];
__device__ float g_si[MAXTOPK];
__device__ float g_sj[MAXTOPK];

// ---------------- packed fp32x2 helpers (B300 FFMA2) -------------------------
__device__ __forceinline__ void ffma2(uint64_t& d, uint64_t a, uint64_t b) {
    asm("fma.rn.f32x2 %0, %1, %2, %0;" : "+l"(d) : "l"(a), "l"(b));
}
__device__ __forceinline__ uint64_t dup2(float s) {
    uint64_t d;
    asm("mov.b64 %0, {%1, %1};" : "=l"(d) : "f"(s));
    return d;
}
__device__ __forceinline__ void unpack2(uint64_t v, float& lo, float& hi) {
    asm("mov.b64 {%0, %1}, %2;" : "=f"(lo), "=f"(hi) : "l"(v));
}

// ---------------- zero -------------------------------------------------------
__global__ void zero_kernel() {
    int idx = blockIdx.x * blockDim.x + threadIdx.x;
    int stride = gridDim.x * blockDim.x;
    for (int i = idx; i < S_*L_; i += stride) g_cnt[i] = 0.f;
    for (int i = idx; i < S_; i += stride) { g_tcnt[i] = 0; }
}

// ---------------- edge histogram ---------------------------------------------
__global__ void edge_hist_kernel(const int* __restrict__ edges, int E) {
    int e = blockIdx.x * blockDim.x + threadIdx.x;
    if (e >= E) return;
    int tgt = edges[e*3+1];
    int lbl = edges[e*3+2];
    atomicAdd(&g_cnt[tgt*L_ + lbl], 1.0f);
    atomicAdd(&g_tcnt[tgt], 1);
}

__global__ void scan_kernel() {
    __shared__ int tmp[S_];
    int t = threadIdx.x;
    int v = g_tcnt[t];
    tmp[t] = v;
    __syncthreads();
    for (int o = 1; o < S_; o <<= 1) {
        int u = (t >= o) ? tmp[t-o] : 0;
        __syncthreads();
        tmp[t] += u;
        __syncthreads();
    }
    g_toff[t] = tmp[t] - v;
    g_tcur[t] = tmp[t] - v;
}

__global__ void edge_scatter_kernel(const int* __restrict__ edges, int E) {
    int e = blockIdx.x * blockDim.x + threadIdx.x;
    if (e >= E) return;
    int tgt = edges[e*3+1];
    int p = atomicAdd(&g_tcur[tgt], 1);
    g_eidx[p] = e;
}

// ---------------- SIMT fp32 GEMM with FFMA2: C = A(MxK,lda) @ B(KxN,ldb) -----
__global__ __launch_bounds__(256)
void gemm_nn_kernel(const float* __restrict__ A0, int lda,
                    const float* __restrict__ B0, int ldb,
                    float* __restrict__ C0, int ldc, int K,
                    size_t strideA, size_t strideB, size_t strideC) {
    __shared__ float As[BK][BM];
    __shared__ float Bs[BK][BN];
    int tid = threadIdx.x;
    int bx = blockIdx.x, by = blockIdx.y, bz = blockIdx.z;
    const float* A = A0 + (size_t)bz * strideA;
    const float* B = B0 + (size_t)bz * strideB;
    float* C = C0 + (size_t)bz * strideC;

    int arow = tid >> 1,  acol = (tid & 1) * 4;
    int brow = tid >> 5,  bcol = (tid & 31) * 4;
    int ty = tid >> 4,    tx = tid & 15;

    uint64_t acc2[8][4];
    uint64_t z2 = dup2(0.f);
#pragma unroll
    for (int i = 0; i < 8; i++)
#pragma unroll
        for (int j = 0; j < 4; j++) acc2[i][j] = z2;

    const float* Aptr = &A[(size_t)(by*BM + arow) * lda];
    float4 pa = *(const float4*)&Aptr[acol];
    float4 pb = *(const float4*)&B[(size_t)brow * ldb + bx*BN + bcol];

    int iters = K / BK;
    for (int kt = 0; kt < iters; kt++) {
        As[acol+0][arow] = pa.x;
        As[acol+1][arow] = pa.y;
        As[acol+2][arow] = pa.z;
        As[acol+3][arow] = pa.w;
        *(float4*)&Bs[brow][bcol] = pb;
        __syncthreads();
        if (kt + 1 < iters) {
            int k0 = (kt+1)*BK;
            pa = *(const float4*)&Aptr[k0 + acol];
            pb = *(const float4*)&B[(size_t)(k0 + brow) * ldb + bx*BN + bcol];
        }
#pragma unroll
        for (int kk = 0; kk < BK; kk++) {
            float4 a0 = *(float4*)&As[kk][ty*4];
            float4 a1 = *(float4*)&As[kk][ty*4+64];
            ulonglong2 bp0 = *(ulonglong2*)&Bs[kk][tx*4];      // (b0,b1),(b2,b3)
            ulonglong2 bp1 = *(ulonglong2*)&Bs[kk][tx*4+64];
            uint64_t ad[8];
            ad[0] = dup2(a0.x); ad[1] = dup2(a0.y);
            ad[2] = dup2(a0.z); ad[3] = dup2(a0.w);
            ad[4] = dup2(a1.x); ad[5] = dup2(a1.y);
            ad[6] = dup2(a1.z); ad[7] = dup2(a1.w);
#pragma unroll
            for (int i = 0; i < 8; i++) {
                ffma2(acc2[i][0], ad[i], bp0.x);
                ffma2(acc2[i][1], ad[i], bp0.y);
                ffma2(acc2[i][2], ad[i], bp1.x);
                ffma2(acc2[i][3], ad[i], bp1.y);
            }
        }
        __syncthreads();
    }

#pragma unroll
    for (int i = 0; i < 8; i++) {
        int r = by*BM + ((i < 4) ? (ty*4 + i) : (64 + ty*4 + i - 4));
        float c0, c1;
        unpack2(acc2[i][0], c0, c1);
        C[(size_t)r * ldc + bx*BN + tx*4]          = c0;
        C[(size_t)r * ldc + bx*BN + tx*4 + 1]      = c1;
        unpack2(acc2[i][1], c0, c1);
        C[(size_t)r * ldc + bx*BN + tx*4 + 2]      = c0;
        C[(size_t)r * ldc + bx*BN + tx*4 + 3]      = c1;
        unpack2(acc2[i][2], c0, c1);
        C[(size_t)r * ldc + bx*BN + 64 + tx*4]     = c0;
        C[(size_t)r * ldc + bx*BN + 64 + tx*4 + 1] = c1;
        unpack2(acc2[i][3], c0, c1);
        C[(size_t)r * ldc + bx*BN + 64 + tx*4 + 2] = c0;
        C[(size_t)r * ldc + bx*BN + 64 + tx*4 + 3] = c1;
    }
}

// ------- gather + GCN epilogue ----------------------------------------------
__global__ __launch_bounds__(256)
void gather_finish_kernel(const float* __restrict__ x,
                          const int* __restrict__ edges,
                          const float* __restrict__ gcn_b) {
    int s = blockIdx.x;
    int tid = threadIdx.x;
    __shared__ float scnt[L_];
    __shared__ int sedge[512];
    if (tid < L_) scnt[tid] = g_cnt[s*L_ + tid];
    __syncthreads();
    float deg = 0.f;
#pragma unroll
    for (int l = 0; l < L_; l++) deg += scnt[l];
    deg = fmaxf(deg, 1.0f);
    float inv = 1.0f / deg;

    float acc0 = 0.f, acc1 = 0.f, acc2v = 0.f;
    for (int l = 0; l < L_; l++) {
        float cv = scnt[l];
        if (cv != 0.f) {
            acc0  += cv * gcn_b[l*H_ + tid];
            acc1  += cv * gcn_b[l*H_ + tid + 256];
            acc2v += cv * gcn_b[l*H_ + tid + 512];
        }
    }
    int lo = g_toff[s];
    int cntE = g_tcnt[s];
    for (int base = 0; base < cntE; base += 256) {
        int m = min(256, cntE - base);
        if (tid < m) {
            int eid = g_eidx[lo + base + tid];
            sedge[tid*2]   = edges[eid*3];
            sedge[tid*2+1] = edges[eid*3+2];
        }
        __syncthreads();
        for (int j = 0; j < m; j++) {
            const float* zr = &g_z[((size_t)sedge[j*2+1] * S_ + sedge[j*2]) * H_];
            acc0  += zr[tid];
            acc1  += zr[tid + 256];
            acc2v += zr[tid + 512];
        }
        __syncthreads();
    }
    g_emb[s*H_ + tid]       = x[s*H_ + tid]       + fmaxf(acc0 * inv, 0.f);
    g_emb[s*H_ + tid + 256] = x[s*H_ + tid + 256] + fmaxf(acc1 * inv, 0.f);
    g_emb[s*H_ + tid + 512] = x[s*H_ + tid + 512] + fmaxf(acc2v * inv, 0.f);
}

// ---------------- per-position attention score ------------------------------
__global__ void row_score_kernel(const float* __restrict__ attn_w,
                                 const float* __restrict__ attn_b) {
    int warp = threadIdx.x >> 5;
    int lane = threadIdx.x & 31;
    int s = blockIdx.x * 8 + warp;
    if (s >= S_) return;
    float p = 0.f;
    for (int h = lane; h < H_; h += 32)
        p += g_emb[s*H_ + h] * attn_w[h];
#pragma unroll
    for (int o = 16; o > 0; o >>= 1)
        p += __shfl_xor_sync(0xffffffffu, p, o);
    if (lane == 0) g_pscore[s] = p + attn_b[0];
}

// ---------------- softmax attention weights per span ------------------------
__global__ void aw_kernel(const int* __restrict__ starts,
                          const int* __restrict__ ends, int nspan) {
    int n = blockIdx.x * blockDim.x + threadIdx.x;
    if (n >= nspan) return;
    int st = starts[n], en = ends[n];
    float sc[SW_];
    float m = -3.4e38f;
#pragma unroll
    for (int w = 0; w < SW_; w++) {
        int pos = st + w;
        int pc = pos < (S_-1) ? pos : (S_-1);
        float sv = g_pscore[pc];
        if (pos > en) sv = -1e9f;
        sc[w] = sv;
        m = fmaxf(m, sv);
    }
    float denom = 0.f;
#pragma unroll
    for (int w = 0; w < SW_; w++) { sc[w] = expf(sc[w] - m); denom += sc[w]; }
    float inv = 1.0f / denom;
#pragma unroll
    for (int w = 0; w < SW_; w++) g_aw[n*SW_ + w] = sc[w] * inv;
}

// ------- mention scores: block per start position ---------------------------
__global__ __launch_bounds__(256)
void mention_kernel(const int* __restrict__ starts, const int* __restrict__ ends,
                    const float* __restrict__ b1, const float* __restrict__ W2,
                    const float* __restrict__ b2p, int nspan) {
    int s = blockIdx.x;
    int lo, hi;
    { int a = 0, b = nspan;
      while (a < b) { int m = (a+b) >> 1; if (starts[m] < s) a = m+1; else b = m; }
      lo = a; }
    { int a = lo, b = nspan;
      while (a < b) { int m = (a+b) >> 1; if (starts[m] < s+1) a = m+1; else b = m; }
      hi = a; }
    int cntS = hi - lo;
    if (cntS == 0) return;

    __shared__ float saw[SW_-1][SW_];
    __shared__ int   sen[SW_-1];
    __shared__ float red[SW_-1];
    int tid = threadIdx.x;
    if (tid < cntS*SW_) saw[tid/SW_][tid%SW_] = g_aw[(lo + tid/SW_)*SW_ + tid%SW_];
    if (tid < cntS) { sen[tid] = ends[lo + tid]; red[tid] = 0.f; }
    __syncthreads();

    float partial[SW_-1];
#pragma unroll
    for (int j = 0; j < SW_-1; j++) partial[j] = 0.f;

    for (int c = tid; c < D_; c += 256) {
        float p1 = g_P[(size_t)s * P_N + c];
        float p3[SW_];
#pragma unroll
        for (int w = 0; w < SW_; w++) {
            int pc = (s + w) < (S_-1) ? (s + w) : (S_-1);
            p3[w] = g_P[(size_t)pc * P_N + 2*D_ + c];
        }
        float b1c = b1[c], w2c = W2[c];
        for (int j = 0; j < cntS; j++) {
            float v = p1 + g_P[(size_t)sen[j] * P_N + D_ + c];
#pragma unroll
            for (int w = 0; w < SW_; w++) v += saw[j][w] * p3[w];
            partial[j] += fmaxf(v + b1c, 0.f) * w2c;
        }
    }
    for (int j = 0; j < cntS; j++) atomicAdd(&red[j], partial[j]);
    __syncthreads();
    if (tid < cntS) g_mscore[lo + tid] = red[tid] + b2p[0];
}

// ---------------- exact top-k by ranking ------------------------------------
__global__ void topk_kernel(int nspan, int ktop) {
    __shared__ float sc[MAXSPAN];
    for (int i = threadIdx.x; i < MAXSPAN; i += blockDim.x)
        sc[i] = (i < nspan) ? g_mscore[i] : -3.4e38f;
    __syncthreads();
    int i = blockIdx.x * blockDim.x + threadIdx.x;
    if (i >= nspan) return;
    float si = sc[i];
    int r = 0;
    for (int j = 0; j < nspan; j++) {
        float sj = sc[j];
        r += (sj > si) || (sj == si && j < i);
    }
    if (r < ktop) g_topk[r] = i;
}

// ----- per-position antecedent dots ------------------------------------------
__global__ void eabc_kernel(const float* __restrict__ antW) {
    int s = blockIdx.x;
    int w = threadIdx.x >> 5;
    int lane = threadIdx.x & 31;
    const float* a = antW + w * H_;
    float p = 0.f;
    for (int h = lane; h < H_; h += 32)
        p += g_emb[s*H_ + h] * a[h];
#pragma unroll
    for (int o = 16; o > 0; o >>= 1)
        p += __shfl_xor_sync(0xffffffffu, p, o);
    if (lane == 0) g_eabc[s*6 + w] = p;
}

__global__ void sisj_kernel(const int* __restrict__ starts,
                            const int* __restrict__ ends, int ktop) {
    int b = blockIdx.x * blockDim.x + threadIdx.x;
    if (b >= ktop) return;
    int n = g_topk[b];
    int st = starts[n], en = ends[n];
    float ci = 0.f, cj = 0.f;
#pragma unroll
    for (int w = 0; w < SW_; w++) {
        int pc = (st + w) < (S_-1) ? (st + w) : (S_-1);
        float a = g_aw[n*SW_ + w];
        ci += a * g_eabc[pc*6 + 2];
        cj += a * g_eabc[pc*6 + 5];
    }
    g_si[b] = g_eabc[st*6 + 0] + g_eabc[en*6 + 1] + ci;
    g_sj[b] = g_eabc[st*6 + 3] + g_eabc[en*6 + 4] + cj;
}

__global__ void final_kernel(float* __restrict__ out,
                             const float* __restrict__ ant_b, int ktop) {
    int id = blockIdx.x * blockDim.x + threadIdx.x;
    int total = ktop * (ktop + 1);
    if (id >= total) return;
    int i = id / (ktop + 1);
    int c = id % (ktop + 1);
    float v;
    if (c == 0) {
        v = 0.f;
    } else {
        int j = c - 1;
        v = (j >= i) ? -10000.0f : (g_si[i] + g_sj[j] + ant_b[0]);
    }
    out[id] = v;
}

// ---------------- host launch -------------------------------------------------
extern "C" void kernel_launch(void* const* d_in, const int* in_sizes, int n_in,
                              void* d_out, int out_size) {
    const float* hidden = (const float*)d_in[0];
    const int*   edges  = (const int*)d_in[1];
    const float* gcnW   = (const float*)d_in[2];
    const float* gcnb   = (const float*)d_in[3];
    const float* attnw  = (const float*)d_in[4];
    const float* attnb  = (const float*)d_in[5];
    const float* msW1   = (const float*)d_in[6];
    const float* msb1   = (const float*)d_in[7];
    const float* msW2   = (const float*)d_in[8];
    const float* msb2   = (const float*)d_in[9];
    const float* antW   = (const float*)d_in[10];
    const float* antb   = (const float*)d_in[11];
    const int*   sstart = (const int*)d_in[12];
    const int*   send   = (const int*)d_in[13];

    int E = in_sizes[1] / 3;
    int nspan = in_sizes[12];
    int ktop = (int)((sqrt(4.0 * (double)out_size + 1.0) - 1.0) / 2.0 + 0.5);
    float* out = (float*)d_out;

    float* zptr;  cudaGetSymbolAddress((void**)&zptr, g_z);
    float* Pptr;  cudaGetSymbolAddress((void**)&Pptr, g_P);
    float* embp;  cudaGetSymbolAddress((void**)&embp, g_emb);

    zero_kernel<<<64, 256>>>();
    edge_hist_kernel<<<(E + 255)/256, 256>>>(edges, E);
    scan_kernel<<<1, S_>>>();
    edge_scatter_kernel<<<(E + 255)/256, 256>>>(edges, E);

    // z[l] = x @ W_l  (batched 50 x (1024x768x768))
    gemm_nn_kernel<<<dim3(H_/BN, S_/BM, L_), 256>>>(
        hidden, H_, gcnW, H_, zptr, H_, H_,
        0, (size_t)H_*H_, (size_t)S_*H_);

    gather_finish_kernel<<<S_, 256>>>(hidden, edges, gcnb);
    row_score_kernel<<<S_/8, 256>>>(attnw, attnb);
    aw_kernel<<<(nspan + 255)/256, 256>>>(sstart, send, nspan);

    // P parts: P[:, part*D : (part+1)*D] = emb @ ms_W1[part*768:(part+1)*768, :]
    for (int part = 0; part < 3; part++) {
        gemm_nn_kernel<<<dim3(D_/BN, S_/BM, 1), 256>>>(
            embp, H_, msW1 + (size_t)part*H_*D_, D_,
            Pptr + (size_t)part*D_, P_N, H_, 0, 0, 0);
    }

    mention_kernel<<<S_, 256>>>(sstart, send, msb1, msW2, msb2, nspan);
    topk_kernel<<<(nspan + 255)/256, 256>>>(nspan, ktop);
    eabc_kernel<<<S_, 192>>>(antW);
    sisj_kernel<<<(ktop + 255)/256, 256>>>(sstart, send, ktop);
    final_kernel<<<(ktop*(ktop+1) + 255)/256, 256>>>(out, antb, ktop);
}

// round 9
// speedup vs baseline: 14.4973x; 1.0221x over previous
#include <cuda_runtime.h>
#include <cuda_fp16.h>
#include <math.h>
#include <stdint.h>

// Problem constants
#define S_ 1024
#define H_ 768
#define L_ 50
#define SW_ 10
#define D_ 2304            // 3*H
#define P_N 6912           // 3*D columns of P = emb @ [W1a|W1b|W1c]
#define MAXSPAN 9216
#define MAXTOPK 1024

// fp16 GEMM tiling
#define BM 128
#define BN 128
#define BK 16

// ---------------- device scratch ---------------------------------------------
__device__ __align__(16) __half g_zh[(size_t)L_*S_*H_];    // 79 MB: z[l][s][d] fp16
__device__ __align__(16) __half g_xh[S_*H_];
__device__ __align__(16) __half g_Wh[(size_t)L_*H_*H_];    // 59 MB
__device__ __align__(16) __half g_W1h[(size_t)D_*D_];      // 10.6 MB
__device__ __align__(16) __half g_embh[S_*H_];
__device__ __align__(16) float g_P[(size_t)S_*P_N];        // 28 MB
__device__ __align__(16) float g_cnt[S_*L_];
__device__ int   g_tcnt[S_];
__device__ int   g_toff[S_];
__device__ int   g_tcur[S_];
__device__ int   g_eidx[65536*2];
__device__ __align__(16) float g_emb[S_*H_];
__device__ __align__(16) float g_pscore[S_];
__device__ __align__(16) float g_aw[MAXSPAN*SW_];
__device__ __align__(16) float g_mscore[MAXSPAN];
__device__ __align__(16) float g_eabc[S_*6];
__device__ int   g_topk[MAXTOPK];
__device__ float g_si[MAXTOPK];
__device__ float g_sj[MAXTOPK];

// ---------------- conversions -------------------------------------------------
__global__ void cvt_half_kernel(const float* __restrict__ src,
                                __half* __restrict__ dst, size_t n4) {
    size_t i = (size_t)blockIdx.x * blockDim.x + threadIdx.x;
    size_t stride = (size_t)gridDim.x * blockDim.x;
    for (; i < n4; i += stride) {
        float4 v = ((const float4*)src)[i];
        __half2 h0 = __floats2half2_rn(v.x, v.y);
        __half2 h1 = __floats2half2_rn(v.z, v.w);
        ((uint2*)dst)[i] = make_uint2(*(uint32_t*)&h0, *(uint32_t*)&h1);
    }
}

// ---------------- zero --------------------------------------------------------
__global__ void zero_kernel() {
    int idx = blockIdx.x * blockDim.x + threadIdx.x;
    int stride = gridDim.x * blockDim.x;
    for (int i = idx; i < S_*L_; i += stride) g_cnt[i] = 0.f;
    for (int i = idx; i < S_; i += stride) { g_tcnt[i] = 0; }
}

// ---------------- edge histogram ----------------------------------------------
__global__ void edge_hist_kernel(const int* __restrict__ edges, int E) {
    int e = blockIdx.x * blockDim.x + threadIdx.x;
    if (e >= E) return;
    int tgt = edges[e*3+1];
    int lbl = edges[e*3+2];
    atomicAdd(&g_cnt[tgt*L_ + lbl], 1.0f);
    atomicAdd(&g_tcnt[tgt], 1);
}

__global__ void scan_kernel() {
    __shared__ int tmp[S_];
    int t = threadIdx.x;
    int v = g_tcnt[t];
    tmp[t] = v;
    __syncthreads();
    for (int o = 1; o < S_; o <<= 1) {
        int u = (t >= o) ? tmp[t-o] : 0;
        __syncthreads();
        tmp[t] += u;
        __syncthreads();
    }
    g_toff[t] = tmp[t] - v;
    g_tcur[t] = tmp[t] - v;
}

__global__ void edge_scatter_kernel(const int* __restrict__ edges, int E) {
    int e = blockIdx.x * blockDim.x + threadIdx.x;
    if (e >= E) return;
    int tgt = edges[e*3+1];
    int p = atomicAdd(&g_tcur[tgt], 1);
    g_eidx[p] = e;
}

// ---------------- fp16 HFMA2 GEMM: C = A(MxK,lda) @ B(KxN,ldb) ----------------
// fp16 accumulate within each BK=16 slab, spilled to fp32.
// OUT_HALF: C stored as half; else float.
template<bool OUT_HALF>
__global__ __launch_bounds__(256)
void gemm_h_kernel(const __half* __restrict__ A0, int lda,
                   const __half* __restrict__ B0, int ldb,
                   void* __restrict__ C0, int ldc, int K,
                   size_t strideA, size_t strideB, size_t strideC) {
    __shared__ __half2 As2[BK][BM];     // duplicated (a,a) pairs: 8 KB
    __shared__ __half  Bs[BK][BN];      // 4 KB
    int tid = threadIdx.x;
    int bx = blockIdx.x, by = blockIdx.y, bz = blockIdx.z;
    const __half* A = A0 + (size_t)bz * strideA;
    const __half* B = B0 + (size_t)bz * strideB;

    int arow = tid >> 1,  ac8 = (tid & 1) * 8;   // A: 128 rows x 16 halfs
    int brow = tid >> 4,  bc8 = (tid & 15) * 8;  // B: 16 rows x 128 halfs
    int ty = tid >> 4,    tx = tid & 15;

    float facc[8][8];
#pragma unroll
    for (int i = 0; i < 8; i++)
#pragma unroll
        for (int j = 0; j < 8; j++) facc[i][j] = 0.f;

    const __half* Aptr = &A[(size_t)(by*BM + arow) * lda + ac8];
    const __half* Bptr = &B[(size_t)brow * ldb + bx*BN + bc8];

    uint4 pa = *(const uint4*)Aptr;
    uint4 pb = *(const uint4*)Bptr;

    int iters = K / BK;
    for (int kt = 0; kt < iters; kt++) {
        {   // store A duplicated into As2 (transposed), B straight
            const __half* ph = (const __half*)&pa;
#pragma unroll
            for (int i = 0; i < 8; i++)
                As2[ac8 + i][arow] = __half2half2(ph[i]);
            *(uint4*)&Bs[brow][bc8] = pb;
        }
        __syncthreads();
        if (kt + 1 < iters) {
            pa = *(const uint4*)(Aptr + (kt+1)*BK);
            pb = *(const uint4*)(Bptr + (size_t)(kt+1)*BK*ldb);
        }

        __half2 hacc[8][4];
        __half2 hz = __float2half2_rn(0.f);
#pragma unroll
        for (int i = 0; i < 8; i++)
#pragma unroll
            for (int j = 0; j < 4; j++) hacc[i][j] = hz;

#pragma unroll
        for (int kk = 0; kk < BK; kk++) {
            __half2 a2[8];
            *(uint4*)&a2[0] = *(uint4*)&As2[kk][ty*4];
            *(uint4*)&a2[4] = *(uint4*)&As2[kk][ty*4 + 64];
            __half2 b2[4];
            *(uint2*)&b2[0] = *(uint2*)&Bs[kk][tx*4];
            *(uint2*)&b2[2] = *(uint2*)&Bs[kk][tx*4 + 64];
#pragma unroll
            for (int i = 0; i < 8; i++) {
                hacc[i][0] = __hfma2(a2[i], b2[0], hacc[i][0]);
                hacc[i][1] = __hfma2(a2[i], b2[1], hacc[i][1]);
                hacc[i][2] = __hfma2(a2[i], b2[2], hacc[i][2]);
                hacc[i][3] = __hfma2(a2[i], b2[3], hacc[i][3]);
            }
        }
        // spill fp16 slab accumulators into fp32
#pragma unroll
        for (int i = 0; i < 8; i++) {
#pragma unroll
            for (int j = 0; j < 4; j++) {
                float2 f = __half22float2(hacc[i][j]);
                facc[i][2*j]     += f.x;
                facc[i][2*j + 1] += f.y;
            }
        }
        __syncthreads();
    }

#pragma unroll
    for (int i = 0; i < 8; i++) {
        int r = by*BM + ((i < 4) ? (ty*4 + i) : (64 + ty*4 + i - 4));
        // col mapping: facc[i][0..3] -> cols tx*4..+3 ; [4..7] -> 64+tx*4..+3
        if (OUT_HALF) {
            __half* C = (__half*)C0 + (size_t)bz * strideC;
            __half2 h01 = __floats2half2_rn(facc[i][0], facc[i][1]);
            __half2 h23 = __floats2half2_rn(facc[i][2], facc[i][3]);
            __half2 h45 = __floats2half2_rn(facc[i][4], facc[i][5]);
            __half2 h67 = __floats2half2_rn(facc[i][6], facc[i][7]);
            *(__half2*)&C[(size_t)r * ldc + bx*BN + tx*4]          = h01;
            *(__half2*)&C[(size_t)r * ldc + bx*BN + tx*4 + 2]      = h23;
            *(__half2*)&C[(size_t)r * ldc + bx*BN + 64 + tx*4]     = h45;
            *(__half2*)&C[(size_t)r * ldc + bx*BN + 64 + tx*4 + 2] = h67;
        } else {
            float* C = (float*)C0 + (size_t)bz * strideC;
            *(float4*)&C[(size_t)r * ldc + bx*BN + tx*4] =
                make_float4(facc[i][0], facc[i][1], facc[i][2], facc[i][3]);
            *(float4*)&C[(size_t)r * ldc + bx*BN + 64 + tx*4] =
                make_float4(facc[i][4], facc[i][5], facc[i][6], facc[i][7]);
        }
    }
}

// ------- gather + GCN epilogue (z in fp16) ------------------------------------
__global__ __launch_bounds__(256)
void gather_finish_kernel(const float* __restrict__ x,
                          const int* __restrict__ edges,
                          const float* __restrict__ gcn_b) {
    int s = blockIdx.x;
    int tid = threadIdx.x;
    __shared__ float scnt[L_];
    __shared__ int sedge[512];
    if (tid < L_) scnt[tid] = g_cnt[s*L_ + tid];
    __syncthreads();
    float deg = 0.f;
#pragma unroll
    for (int l = 0; l < L_; l++) deg += scnt[l];
    deg = fmaxf(deg, 1.0f);
    float inv = 1.0f / deg;

    float acc0 = 0.f, acc1 = 0.f, acc2v = 0.f;
    for (int l = 0; l < L_; l++) {
        float cv = scnt[l];
        if (cv != 0.f) {
            acc0  += cv * gcn_b[l*H_ + tid];
            acc1  += cv * gcn_b[l*H_ + tid + 256];
            acc2v += cv * gcn_b[l*H_ + tid + 512];
        }
    }
    int lo = g_toff[s];
    int cntE = g_tcnt[s];
    for (int base = 0; base < cntE; base += 256) {
        int m = min(256, cntE - base);
        if (tid < m) {
            int eid = g_eidx[lo + base + tid];
            sedge[tid*2]   = edges[eid*3];
            sedge[tid*2+1] = edges[eid*3+2];
        }
        __syncthreads();
        for (int j = 0; j < m; j++) {
            const __half* zr = &g_zh[((size_t)sedge[j*2+1] * S_ + sedge[j*2]) * H_];
            acc0  += __half2float(zr[tid]);
            acc1  += __half2float(zr[tid + 256]);
            acc2v += __half2float(zr[tid + 512]);
        }
        __syncthreads();
    }
    float e0 = x[s*H_ + tid]       + fmaxf(acc0 * inv, 0.f);
    float e1 = x[s*H_ + tid + 256] + fmaxf(acc1 * inv, 0.f);
    float e2 = x[s*H_ + tid + 512] + fmaxf(acc2v * inv, 0.f);
    g_emb[s*H_ + tid]        = e0;
    g_emb[s*H_ + tid + 256]  = e1;
    g_emb[s*H_ + tid + 512]  = e2;
    g_embh[s*H_ + tid]       = __float2half_rn(e0);
    g_embh[s*H_ + tid + 256] = __float2half_rn(e1);
    g_embh[s*H_ + tid + 512] = __float2half_rn(e2);
}

// ---------------- per-position attention score --------------------------------
__global__ void row_score_kernel(const float* __restrict__ attn_w,
                                 const float* __restrict__ attn_b) {
    int warp = threadIdx.x >> 5;
    int lane = threadIdx.x & 31;
    int s = blockIdx.x * 8 + warp;
    if (s >= S_) return;
    float p = 0.f;
    for (int h = lane; h < H_; h += 32)
        p += g_emb[s*H_ + h] * attn_w[h];
#pragma unroll
    for (int o = 16; o > 0; o >>= 1)
        p += __shfl_xor_sync(0xffffffffu, p, o);
    if (lane == 0) g_pscore[s] = p + attn_b[0];
}

// ---------------- softmax attention weights per span --------------------------
__global__ void aw_kernel(const int* __restrict__ starts,
                          const int* __restrict__ ends, int nspan) {
    int n = blockIdx.x * blockDim.x + threadIdx.x;
    if (n >= nspan) return;
    int st = starts[n], en = ends[n];
    float sc[SW_];
    float m = -3.4e38f;
#pragma unroll
    for (int w = 0; w < SW_; w++) {
        int pos = st + w;
        int pc = pos < (S_-1) ? pos : (S_-1);
        float sv = g_pscore[pc];
        if (pos > en) sv = -1e9f;
        sc[w] = sv;
        m = fmaxf(m, sv);
    }
    float denom = 0.f;
#pragma unroll
    for (int w = 0; w < SW_; w++) { sc[w] = expf(sc[w] - m); denom += sc[w]; }
    float inv = 1.0f / denom;
#pragma unroll
    for (int w = 0; w < SW_; w++) g_aw[n*SW_ + w] = sc[w] * inv;
}

// ------- mention scores: block per start position -----------------------------
__global__ __launch_bounds__(256)
void mention_kernel(const int* __restrict__ starts, const int* __restrict__ ends,
                    const float* __restrict__ b1, const float* __restrict__ W2,
                    const float* __restrict__ b2p, int nspan) {
    int s = blockIdx.x;
    int lo, hi;
    { int a = 0, b = nspan;
      while (a < b) { int m = (a+b) >> 1; if (starts[m] < s) a = m+1; else b = m; }
      lo = a; }
    { int a = lo, b = nspan;
      while (a < b) { int m = (a+b) >> 1; if (starts[m] < s+1) a = m+1; else b = m; }
      hi = a; }
    int cntS = hi - lo;
    if (cntS == 0) return;

    __shared__ float saw[SW_-1][SW_];
    __shared__ int   sen[SW_-1];
    __shared__ float red[SW_-1];
    int tid = threadIdx.x;
    if (tid < cntS*SW_) saw[tid/SW_][tid%SW_] = g_aw[(lo + tid/SW_)*SW_ + tid%SW_];
    if (tid < cntS) { sen[tid] = ends[lo + tid]; red[tid] = 0.f; }
    __syncthreads();

    float partial[SW_-1];
#pragma unroll
    for (int j = 0; j < SW_-1; j++) partial[j] = 0.f;

    for (int c = tid; c < D_; c += 256) {
        float p1 = g_P[(size_t)s * P_N + c];
        float p3[SW_];
#pragma unroll
        for (int w = 0; w < SW_; w++) {
            int pc = (s + w) < (S_-1) ? (s + w) : (S_-1);
            p3[w] = g_P[(size_t)pc * P_N + 2*D_ + c];
        }
        float b1c = b1[c], w2c = W2[c];
        for (int j = 0; j < cntS; j++) {
            float v = p1 + g_P[(size_t)sen[j] * P_N + D_ + c];
#pragma unroll
            for (int w = 0; w < SW_; w++) v += saw[j][w] * p3[w];
            partial[j] += fmaxf(v + b1c, 0.f) * w2c;
        }
    }
    for (int j = 0; j < cntS; j++) atomicAdd(&red[j], partial[j]);
    __syncthreads();
    if (tid < cntS) g_mscore[lo + tid] = red[tid] + b2p[0];
}

// ---------------- exact top-k by ranking --------------------------------------
__global__ void topk_kernel(int nspan, int ktop) {
    __shared__ float sc[MAXSPAN];
    for (int i = threadIdx.x; i < MAXSPAN; i += blockDim.x)
        sc[i] = (i < nspan) ? g_mscore[i] : -3.4e38f;
    __syncthreads();
    int i = blockIdx.x * blockDim.x + threadIdx.x;
    if (i >= nspan) return;
    float si = sc[i];
    int r = 0;
    for (int j = 0; j < nspan; j++) {
        float sj = sc[j];
        r += (sj > si) || (sj == si && j < i);
    }
    if (r < ktop) g_topk[r] = i;
}

// ----- per-position antecedent dots --------------------------------------------
__global__ void eabc_kernel(const float* __restrict__ antW) {
    int s = blockIdx.x;
    int w = threadIdx.x >> 5;
    int lane = threadIdx.x & 31;
    const float* a = antW + w * H_;
    float p = 0.f;
    for (int h = lane; h < H_; h += 32)
        p += g_emb[s*H_ + h] * a[h];
#pragma unroll
    for (int o = 16; o > 0; o >>= 1)
        p += __shfl_xor_sync(0xffffffffu, p, o);
    if (lane == 0) g_eabc[s*6 + w] = p;
}

__global__ void sisj_kernel(const int* __restrict__ starts,
                            const int* __restrict__ ends, int ktop) {
    int b = blockIdx.x * blockDim.x + threadIdx.x;
    if (b >= ktop) return;
    int n = g_topk[b];
    int st = starts[n], en = ends[n];
    float ci = 0.f, cj = 0.f;
#pragma unroll
    for (int w = 0; w < SW_; w++) {
        int pc = (st + w) < (S_-1) ? (st + w) : (S_-1);
        float a = g_aw[n*SW_ + w];
        ci += a * g_eabc[pc*6 + 2];
        cj += a * g_eabc[pc*6 + 5];
    }
    g_si[b] = g_eabc[st*6 + 0] + g_eabc[en*6 + 1] + ci;
    g_sj[b] = g_eabc[st*6 + 3] + g_eabc[en*6 + 4] + cj;
}

__global__ void final_kernel(float* __restrict__ out,
                             const float* __restrict__ ant_b, int ktop) {
    int id = blockIdx.x * blockDim.x + threadIdx.x;
    int total = ktop * (ktop + 1);
    if (id >= total) return;
    int i = id / (ktop + 1);
    int c = id % (ktop + 1);
    float v;
    if (c == 0) {
        v = 0.f;
    } else {
        int j = c - 1;
        v = (j >= i) ? -10000.0f : (g_si[i] + g_sj[j] + ant_b[0]);
    }
    out[id] = v;
}

// ---------------- host launch ---------------------------------------------------
extern "C" void kernel_launch(void* const* d_in, const int* in_sizes, int n_in,
                              void* d_out, int out_size) {
    const float* hidden = (const float*)d_in[0];
    const int*   edges  = (const int*)d_in[1];
    const float* gcnW   = (const float*)d_in[2];
    const float* gcnb   = (const float*)d_in[3];
    const float* attnw  = (const float*)d_in[4];
    const float* attnb  = (const float*)d_in[5];
    const float* msW1   = (const float*)d_in[6];
    const float* msb1   = (const float*)d_in[7];
    const float* msW2   = (const float*)d_in[8];
    const float* msb2   = (const float*)d_in[9];
    const float* antW   = (const float*)d_in[10];
    const float* antb   = (const float*)d_in[11];
    const int*   sstart = (const int*)d_in[12];
    const int*   send   = (const int*)d_in[13];

    int E = in_sizes[1] / 3;
    int nspan = in_sizes[12];
    int ktop = (int)((sqrt(4.0 * (double)out_size + 1.0) - 1.0) / 2.0 + 0.5);
    float* out = (float*)d_out;

    __half* xh;   cudaGetSymbolAddress((void**)&xh, g_xh);
    __half* Wh;   cudaGetSymbolAddress((void**)&Wh, g_Wh);
    __half* W1h;  cudaGetSymbolAddress((void**)&W1h, g_W1h);
    __half* zh;   cudaGetSymbolAddress((void**)&zh, g_zh);
    __half* embh; cudaGetSymbolAddress((void**)&embh, g_embh);
    float*  Pptr; cudaGetSymbolAddress((void**)&Pptr, g_P);

    zero_kernel<<<64, 256>>>();
    edge_hist_kernel<<<(E + 255)/256, 256>>>(edges, E);
    scan_kernel<<<1, S_>>>();
    edge_scatter_kernel<<<(E + 255)/256, 256>>>(edges, E);

    // fp32 -> fp16 conversions
    cvt_half_kernel<<<256, 256>>>(hidden, xh, (size_t)S_*H_/4);
    cvt_half_kernel<<<2048, 256>>>(gcnW, Wh, (size_t)L_*H_*H_/4);
    cvt_half_kernel<<<1024, 256>>>(msW1, W1h, (size_t)D_*D_/4);

    // z[l] = x @ W_l  (batched 50 x (1024x768x768)), fp16 in/out
    gemm_h_kernel<true><<<dim3(H_/BN, S_/BM, L_), 256>>>(
        xh, H_, Wh, H_, zh, H_, H_,
        0, (size_t)H_*H_, (size_t)S_*H_);

    gather_finish_kernel<<<S_, 256>>>(hidden, edges, gcnb);
    row_score_kernel<<<S_/8, 256>>>(attnw, attnb);
    aw_kernel<<<(nspan + 255)/256, 256>>>(sstart, send, nspan);

    // P parts: P[:, part*D : (part+1)*D] = emb @ ms_W1[part*768:(part+1)*768, :]
    for (int part = 0; part < 3; part++) {
        gemm_h_kernel<false><<<dim3(D_/BN, S_/BM, 1), 256>>>(
            embh, H_, W1h + (size_t)part*H_*D_, D_,
            Pptr + (size_t)part*D_, P_N, H_, 0, 0, 0);
    }

    mention_kernel<<<S_, 256>>>(sstart, send, msb1, msW2, msb2, nspan);
    topk_kernel<<<(nspan + 255)/256, 256>>>(nspan, ktop);
    eabc_kernel<<<S_, 192>>>(antW);
    sisj_kernel<<<(ktop + 255)/256, 256>>>(sstart, send, ktop);
    final_kernel<<<(ktop*(ktop+1) + 255)/256, 256>>>(out, antb, ktop);
}